// round 14
// baseline (speedup 1.0000x reference)
#include <cuda_runtime.h>
#include <cuda_bf16.h>
#include <cstdint>

// Gridding: trilinear scatter of B=32 x N=262144 points into per-batch 64^3 grids.
// out[b, (x*64 + y)*64 + z], fp32. scale s=32 (half-extent), G=64.
//
// R14 == R4 (design frozen pending first successful GPU hold; 14x broker
// timeout): one thread per point; the 8 corner updates form 4 z-pairs
// {iz, iz+1}. flat ≡ iz (mod 4), so when iz&3 < 3 the pair lies inside one
// 16B-aligned window -> a single red.global.add.v4.f32 (inline PTX) with zeros
// in unused lanes; otherwise two scalar REDs. ~42M LTS atomic transactions
// instead of 67M. Output (33.5 MB) is fully L2-resident.

#define S_CONST 32
#define GDIM 64
#define G2 (GDIM * GDIM)
#define G3 (GDIM * GDIM * GDIM)
#define TPB 256

__global__ __launch_bounds__(TPB) void zero_kernel(float4* __restrict__ out, int n4) {
    int i = blockIdx.x * blockDim.x + threadIdx.x;
    if (i < n4) out[i] = make_float4(0.f, 0.f, 0.f, 0.f);
}

// Vector no-return atomic add (sm_90+ PTX; no CUDA-header overload dependency).
__device__ __forceinline__ void red_add_v4(float* addr, float a, float b,
                                           float c, float d) {
    asm volatile("red.global.add.v4.f32 [%0], {%1, %2, %3, %4};"
                 :: "l"(addr), "f"(a), "f"(b), "f"(c), "f"(d)
                 : "memory");
}

__device__ __forceinline__ void red_add_f32(float* addr, float v) {
    asm volatile("red.global.add.f32 [%0], %1;"
                 :: "l"(addr), "f"(v)
                 : "memory");
}

// Scatter one z-pair (w0 -> g[f], w1 -> g[f+1]).
__device__ __forceinline__ void scatter_pair(float* __restrict__ g, int f,
                                             float w0, float w1) {
    const int lane = f & 3;
    if (lane < 3) {
        float v[4] = {0.f, 0.f, 0.f, 0.f};
        v[lane]     = w0;
        v[lane + 1] = w1;
        red_add_v4(g + (f & ~3), v[0], v[1], v[2], v[3]);
    } else {
        red_add_f32(g + f,     w0);
        red_add_f32(g + f + 1, w1);
    }
}

__global__ __launch_bounds__(TPB) void gridding_kernel(
    const float* __restrict__ pt,   // [B, N, 3]
    float* __restrict__ out,        // [B, G3]
    int N)
{
    const int p = blockIdx.x * blockDim.x + threadIdx.x;
    if (p >= N) return;
    const int b = blockIdx.y;

    // 32-bit indexing: B*N*3 = 25.2M and B*G3 = 8.4M, both < 2^31
    const int in_base = (b * N + p) * 3;
    const float x = pt[in_base + 0] * (float)S_CONST;
    const float y = pt[in_base + 1] * (float)S_CONST;
    const float z = pt[in_base + 2] * (float)S_CONST;

    // reference semantics: drop points whose scaled-coordinate sum is exactly 0
    // (x*32 is exact; sum order matches jnp.sum left-assoc)
    if (x + y + z == 0.0f) return;

    const float lx = floorf(x), ly = floorf(y), lz = floorf(z);
    const float fx = x - lx, fy = y - ly, fz = z - lz;

    // lower-corner index clipped to [0, G-2]; frac from UNCLIPPED floor (matches ref)
    int ix = (int)lx + S_CONST;
    int iy = (int)ly + S_CONST;
    int iz = (int)lz + S_CONST;
    ix = min(max(ix, 0), GDIM - 2);
    iy = min(max(iy, 0), GDIM - 2);
    iz = min(max(iz, 0), GDIM - 2);

    const float wx0 = 1.0f - fx, wx1 = fx;
    const float wy0 = 1.0f - fy, wy1 = fy;
    const float wz0 = 1.0f - fz, wz1 = fz;

    float* __restrict__ g = out + b * G3;
    const int base = (ix * GDIM + iy) * GDIM + iz;

    // four z-pairs: (x0,y0), (x0,y1), (x1,y0), (x1,y1)
    scatter_pair(g, base,             wx0 * wy0 * wz0, wx0 * wy0 * wz1);
    scatter_pair(g, base + GDIM,      wx0 * wy1 * wz0, wx0 * wy1 * wz1);
    scatter_pair(g, base + G2,        wx1 * wy0 * wz0, wx1 * wy0 * wz1);
    scatter_pair(g, base + G2 + GDIM, wx1 * wy1 * wz0, wx1 * wy1 * wz1);
}

extern "C" void kernel_launch(void* const* d_in, const int* in_sizes, int n_in,
                              void* d_out, int out_size) {
    const float* pt = (const float*)d_in[0];
    float* out = (float*)d_out;

    const int B = out_size / G3;                 // 32
    const int N = (in_sizes[0] / 3) / B;         // 262144

    // zero the poisoned output (harness poisons to 0xAA)
    const int n4 = out_size / 4;
    zero_kernel<<<(n4 + TPB - 1) / TPB, TPB>>>((float4*)out, n4);

    dim3 grid((N + TPB - 1) / TPB, B);
    gridding_kernel<<<grid, TPB>>>(pt, out, N);
}

// round 17
// speedup vs baseline: 1.0034x; 1.0034x over previous
#include <cuda_runtime.h>
#include <cuda_bf16.h>
#include <cstdint>

// Gridding: trilinear scatter of B=32 x N=262144 points into per-batch 64^3 grids.
// out[b, (x*64 + y)*64 + z], fp32. scale s=32 (half-extent), G=64.
//
// R17 == R15 (experiment pending; repeated broker timeouts): baseline R14 =
// 207us, L2=84.4% (LTS atomic path binding), DRAM=8.7%, issue=23.4%. Tests
// per-lane vs per-transaction LTS cost: z-pair REDs at minimal width -- v2
// when 8B-aligned (f&3 in {0,2}), v4 straddle for f&3==1, two scalars for
// f&3==3. Transactions unchanged (1.25/pair), lane-work 3.5 -> 2.5 lanes/pair.
// Predict ~155-165us if per-lane, neutral if per-txn.

#define S_CONST 32
#define GDIM 64
#define G2 (GDIM * GDIM)
#define G3 (GDIM * GDIM * GDIM)
#define TPB 256

__global__ __launch_bounds__(TPB) void zero_kernel(float4* __restrict__ out, int n4) {
    int i = blockIdx.x * blockDim.x + threadIdx.x;
    if (i < n4) out[i] = make_float4(0.f, 0.f, 0.f, 0.f);
}

__device__ __forceinline__ void red_add_v4(float* addr, float a, float b,
                                           float c, float d) {
    asm volatile("red.global.add.v4.f32 [%0], {%1, %2, %3, %4};"
                 :: "l"(addr), "f"(a), "f"(b), "f"(c), "f"(d)
                 : "memory");
}

__device__ __forceinline__ void red_add_v2(float* addr, float a, float b) {
    asm volatile("red.global.add.v2.f32 [%0], {%1, %2};"
                 :: "l"(addr), "f"(a), "f"(b)
                 : "memory");
}

__device__ __forceinline__ void red_add_f32(float* addr, float v) {
    asm volatile("red.global.add.f32 [%0], %1;"
                 :: "l"(addr), "f"(v)
                 : "memory");
}

// Scatter one z-pair (w0 -> g[f], w1 -> g[f+1]) with minimal lane footprint.
// All four pairs of a point share the same (f & 3), so a thread takes one arm.
__device__ __forceinline__ void scatter_pair(float* __restrict__ g, int f,
                                             float w0, float w1) {
    const int lane = f & 3;
    if ((lane & 1) == 0) {
        // f even -> 8B-aligned pair: exact v2, 2/2 lanes useful
        red_add_v2(g + f, w0, w1);
    } else if (lane == 1) {
        // pair straddles middle of the 16B window: v4 with lanes 1,2
        red_add_v4(g + (f & ~3), 0.f, w0, w1, 0.f);
    } else {
        // lane == 3: pair crosses the 16B boundary: two scalars
        red_add_f32(g + f,     w0);
        red_add_f32(g + f + 1, w1);
    }
}

__global__ __launch_bounds__(TPB) void gridding_kernel(
    const float* __restrict__ pt,   // [B, N, 3]
    float* __restrict__ out,        // [B, G3]
    int N)
{
    const int p = blockIdx.x * blockDim.x + threadIdx.x;
    if (p >= N) return;
    const int b = blockIdx.y;

    // 32-bit indexing: B*N*3 = 25.2M and B*G3 = 8.4M, both < 2^31
    const int in_base = (b * N + p) * 3;
    const float x = pt[in_base + 0] * (float)S_CONST;
    const float y = pt[in_base + 1] * (float)S_CONST;
    const float z = pt[in_base + 2] * (float)S_CONST;

    // reference semantics: drop points whose scaled-coordinate sum is exactly 0
    if (x + y + z == 0.0f) return;

    const float lx = floorf(x), ly = floorf(y), lz = floorf(z);
    const float fx = x - lx, fy = y - ly, fz = z - lz;

    // lower-corner index clipped to [0, G-2]; frac from UNCLIPPED floor (matches ref)
    int ix = (int)lx + S_CONST;
    int iy = (int)ly + S_CONST;
    int iz = (int)lz + S_CONST;
    ix = min(max(ix, 0), GDIM - 2);
    iy = min(max(iy, 0), GDIM - 2);
    iz = min(max(iz, 0), GDIM - 2);

    const float wx0 = 1.0f - fx, wx1 = fx;
    const float wy0 = 1.0f - fy, wy1 = fy;
    const float wz0 = 1.0f - fz, wz1 = fz;

    float* __restrict__ g = out + b * G3;
    const int base = (ix * GDIM + iy) * GDIM + iz;

    // four z-pairs: (x0,y0), (x0,y1), (x1,y0), (x1,y1)
    scatter_pair(g, base,             wx0 * wy0 * wz0, wx0 * wy0 * wz1);
    scatter_pair(g, base + GDIM,      wx0 * wy1 * wz0, wx0 * wy1 * wz1);
    scatter_pair(g, base + G2,        wx1 * wy0 * wz0, wx1 * wy0 * wz1);
    scatter_pair(g, base + G2 + GDIM, wx1 * wy1 * wz0, wx1 * wy1 * wz1);
}

extern "C" void kernel_launch(void* const* d_in, const int* in_sizes, int n_in,
                              void* d_out, int out_size) {
    const float* pt = (const float*)d_in[0];
    float* out = (float*)d_out;

    const int B = out_size / G3;                 // 32
    const int N = (in_sizes[0] / 3) / B;         // 262144

    // zero the poisoned output (harness poisons to 0xAA)
    const int n4 = out_size / 4;
    zero_kernel<<<(n4 + TPB - 1) / TPB, TPB>>>((float4*)out, n4);

    dim3 grid((N + TPB - 1) / TPB, B);
    gridding_kernel<<<grid, TPB>>>(pt, out, N);
}